// round 4
// baseline (speedup 1.0000x reference)
#include <cuda_runtime.h>
#include <math.h>

#define Bsz 64
#define Ssz 512
#define Dsz 1536
#define FEAT (4*Dsz)      // 6144
#define H1 1024
#define NCH 8             // s-chunks in attention kernel
#define CHS (Ssz/NCH)     // 64
#define QKSPLIT 12        // split-K for Q gemm (K=1536 -> 128 per split)
#define MKSPLIT 16        // split-K for MLP gemm (K=6144 -> 384 per split)

// ---------------- scratch (static device globals; no allocation) ----------------
__device__ float g_ent[2*Bsz*Dsz];                 // rows: [0..63]=entity2, [64..127]=entity1
__device__ float g_qp[QKSPLIT*2*Bsz*Dsz];          // Q gemm partials [ks][128][1536]
__device__ float g_q[2*Bsz*Dsz];                   // q rows: [b]=q2, [64+b]=q1
__device__ float g_accP[2*Bsz*NCH*Dsz];            // attention partial weighted sums
__device__ float g_mP[2*Bsz*NCH];
__device__ float g_lP[2*Bsz*NCH];
__device__ float g_feat[Bsz*FEAT];
__device__ float g_hp[MKSPLIT*Bsz*H1];             // MLP partials

// =====================================================================
// Kernel A: entity masked means (entity spans are tiny: <=7 rows each)
// =====================================================================
__global__ void k_entities(const float* __restrict__ x, const int* __restrict__ locs)
{
    int b = blockIdx.x;
    int l0 = locs[b*4+0], l1 = locs[b*4+1], l2 = locs[b*4+2], l3 = locs[b*4+3];
    float c1 = (float)((l1 - l0 - 1) > 0 ? (l1 - l0 - 1) : 1);
    float c2 = (float)((l3 - l2 - 1) > 0 ? (l3 - l2 - 1) : 1);
    const float* xb = x + (size_t)b * Ssz * Dsz;
    for (int d = threadIdx.x; d < Dsz; d += blockDim.x) {
        float s1 = 0.f, s2 = 0.f;
        for (int s = l0 + 1; s < l1; ++s) s1 += xb[(size_t)s*Dsz + d];
        for (int s = l2 + 1; s < l3; ++s) s2 += xb[(size_t)s*Dsz + d];
        g_ent[(size_t)(0*Bsz + b)*Dsz + d] = s2 / c2;   // entity2
        g_ent[(size_t)(1*Bsz + b)*Dsz + d] = s1 / c1;   // entity1
    }
}

// =====================================================================
// Kernel B: Q = E @ W_in^T   (M=128, N=1536, K=1536), split-K partials
// BM=128, BN=128, BK=16, 256 threads, 8x8 microtile
// =====================================================================
__global__ void __launch_bounds__(256) k_qgemm(const float* __restrict__ Win)
{
    __shared__ float Es[16][128];
    __shared__ float Ws[16][128];
    int n0 = blockIdx.x * 128;
    int k0 = blockIdx.y * 128;
    int t = threadIdx.x;
    int tx = t & 15, ty = t >> 4;
    float acc[8][8];
    #pragma unroll
    for (int i = 0; i < 8; ++i)
        #pragma unroll
        for (int j = 0; j < 8; ++j) acc[i][j] = 0.f;

    int r  = t >> 1;
    int kp = (t & 1) * 8;

    for (int kt = 0; kt < 8; ++kt) {
        int kb = k0 + kt * 16;
        float4 e0 = *(const float4*)(g_ent + (size_t)r*Dsz + kb + kp);
        float4 e1 = *(const float4*)(g_ent + (size_t)r*Dsz + kb + kp + 4);
        float4 w0 = *(const float4*)(Win + (size_t)(n0 + r)*Dsz + kb + kp);
        float4 w1 = *(const float4*)(Win + (size_t)(n0 + r)*Dsz + kb + kp + 4);
        __syncthreads();
        Es[kp+0][r]=e0.x; Es[kp+1][r]=e0.y; Es[kp+2][r]=e0.z; Es[kp+3][r]=e0.w;
        Es[kp+4][r]=e1.x; Es[kp+5][r]=e1.y; Es[kp+6][r]=e1.z; Es[kp+7][r]=e1.w;
        Ws[kp+0][r]=w0.x; Ws[kp+1][r]=w0.y; Ws[kp+2][r]=w0.z; Ws[kp+3][r]=w0.w;
        Ws[kp+4][r]=w1.x; Ws[kp+5][r]=w1.y; Ws[kp+6][r]=w1.z; Ws[kp+7][r]=w1.w;
        __syncthreads();
        #pragma unroll
        for (int kk = 0; kk < 16; ++kk) {
            float4 a0 = *(const float4*)&Es[kk][ty*8];
            float4 a1 = *(const float4*)&Es[kk][ty*8+4];
            float4 b0 = *(const float4*)&Ws[kk][tx*8];
            float4 b1 = *(const float4*)&Ws[kk][tx*8+4];
            float av[8] = {a0.x,a0.y,a0.z,a0.w,a1.x,a1.y,a1.z,a1.w};
            float bv[8] = {b0.x,b0.y,b0.z,b0.w,b1.x,b1.y,b1.z,b1.w};
            #pragma unroll
            for (int i = 0; i < 8; ++i)
                #pragma unroll
                for (int j = 0; j < 8; ++j)
                    acc[i][j] += av[i]*bv[j];
        }
    }
    #pragma unroll
    for (int i = 0; i < 8; ++i) {
        int m = ty*8 + i;
        float* dst = g_qp + ((size_t)blockIdx.y * 128 + m)*Dsz + n0 + tx*8;
        *(float4*)dst       = make_float4(acc[i][0],acc[i][1],acc[i][2],acc[i][3]);
        *(float4*)(dst + 4) = make_float4(acc[i][4],acc[i][5],acc[i][6],acc[i][7]);
    }
}

__global__ void k_qreduce()
{
    int i = blockIdx.x * 512 + threadIdx.x;   // 384*512 == 2*Bsz*Dsz
    float s = 0.f;
    #pragma unroll
    for (int p = 0; p < QKSPLIT; ++p) s += g_qp[(size_t)p * (2*Bsz*Dsz) + i];
    g_q[i] = s;
}

// =====================================================================
// Kernel C: fused scores + online softmax + weighted accumulation
// grid = 64 batches * 8 s-chunks, 384 threads, each thread owns 4 contiguous
// channels (float4 loads). Online softmax over masked rows only.
// =====================================================================
__global__ void __launch_bounds__(384) k_attn(const float* __restrict__ x,
                                              const int* __restrict__ locs,
                                              const int* __restrict__ seps)
{
    int blk = blockIdx.x;
    int b = blk >> 3, ch = blk & 7;
    int t = threadIdx.x;
    int L0 = locs[b*4+0], L1 = locs[b*4+1], L2 = locs[b*4+2], L3 = locs[b*4+3];
    int S0 = seps[b*2+0], S1 = seps[b*2+1];

    float4 q2v = *(const float4*)(g_q + (size_t)b*Dsz + 4*t);
    float4 q1v = *(const float4*)(g_q + (size_t)(Bsz + b)*Dsz + 4*t);

    float acc2[4] = {0.f,0.f,0.f,0.f}, acc1[4] = {0.f,0.f,0.f,0.f};
    const float NEGINF = __int_as_float(0xff800000);
    float m2v = NEGINF, l2v = 0.f, m1v = NEGINF, l1v = 0.f;

    __shared__ float red[16][12];
    __shared__ float fin[16];

    const float* xb = x + ((size_t)b * Ssz + (size_t)ch * CHS) * Dsz;
    int lane = t & 31, wid = t >> 5;   // 12 warps

    for (int g = 0; g < CHS/8; ++g) {
        int sbase = ch*CHS + g*8;
        float xr[8][4];
        float p[16];
        bool i1[8], i2[8];
        #pragma unroll
        for (int u = 0; u < 8; ++u) {
            int s = sbase + u;
            i1[u] = (s <= L0) || ((s >= L1) && (s < S0));
            i2[u] = ((s >= S1) && (s <= L2)) || (s >= L3);
            if (i1[u] || i2[u]) {
                float4 v = *(const float4*)(xb + (size_t)(g*8 + u) * Dsz + 4*t);
                xr[u][0]=v.x; xr[u][1]=v.y; xr[u][2]=v.z; xr[u][3]=v.w;
            } else {
                xr[u][0]=0.f; xr[u][1]=0.f; xr[u][2]=0.f; xr[u][3]=0.f;
            }
            float d2 = q2v.x*xr[u][0] + q2v.y*xr[u][1] + q2v.z*xr[u][2] + q2v.w*xr[u][3];
            float d1 = q1v.x*xr[u][0] + q1v.y*xr[u][1] + q1v.z*xr[u][2] + q1v.w*xr[u][3];
            p[2*u]   = i2[u] ? d2 : 0.f;
            p[2*u+1] = i1[u] ? d1 : 0.f;
        }
        // two-stage reduce of 16 values over 384 threads
        #pragma unroll
        for (int v = 0; v < 16; ++v) {
            float val = p[v];
            val += __shfl_down_sync(0xffffffffu, val, 16);
            val += __shfl_down_sync(0xffffffffu, val, 8);
            val += __shfl_down_sync(0xffffffffu, val, 4);
            val += __shfl_down_sync(0xffffffffu, val, 2);
            val += __shfl_down_sync(0xffffffffu, val, 1);
            if (lane == 0) red[v][wid] = val;
        }
        __syncthreads();
        if (wid == 0 && lane < 16) {
            float ssum = 0.f;
            #pragma unroll
            for (int w = 0; w < 12; ++w) ssum += red[lane][w];
            fin[lane] = ssum;
        }
        __syncthreads();
        // online softmax update (all threads redundantly, identical scalars)
        #pragma unroll
        for (int u = 0; u < 8; ++u) {
            if (i2[u]) {
                float sc = fin[2*u];
                float nm = fmaxf(m2v, sc);
                float scale = expf(m2v - nm);
                float w = expf(sc - nm);
                l2v = l2v*scale + w;
                #pragma unroll
                for (int j = 0; j < 4; ++j) acc2[j] = acc2[j]*scale + w*xr[u][j];
                m2v = nm;
            }
            if (i1[u]) {
                float sc = fin[2*u+1];
                float nm = fmaxf(m1v, sc);
                float scale = expf(m1v - nm);
                float w = expf(sc - nm);
                l1v = l1v*scale + w;
                #pragma unroll
                for (int j = 0; j < 4; ++j) acc1[j] = acc1[j]*scale + w*xr[u][j];
                m1v = nm;
            }
        }
        __syncthreads();   // protect fin before next group's overwrite
    }

    size_t base2 = ((size_t)(0*Bsz + b)*NCH + ch)*Dsz + 4*t;
    size_t base1 = ((size_t)(1*Bsz + b)*NCH + ch)*Dsz + 4*t;
    *(float4*)(g_accP + base2) = make_float4(acc2[0],acc2[1],acc2[2],acc2[3]);
    *(float4*)(g_accP + base1) = make_float4(acc1[0],acc1[1],acc1[2],acc1[3]);
    if (t == 0) {
        g_mP[(0*Bsz + b)*NCH + ch] = m2v;  g_lP[(0*Bsz + b)*NCH + ch] = l2v;
        g_mP[(1*Bsz + b)*NCH + ch] = m1v;  g_lP[(1*Bsz + b)*NCH + ch] = l1v;
    }
}

// =====================================================================
// Kernel D: merge chunk partials + assemble feat = [attn2, attn1, x[:,0], entity2]
// =====================================================================
__global__ void k_merge(const float* __restrict__ x)
{
    int b = blockIdx.x, t = threadIdx.x;   // 512 threads

    float cf2[NCH], cf1[NCH];
    {
        float M = __int_as_float(0xff800000);
        for (int c = 0; c < NCH; ++c) M = fmaxf(M, g_mP[(0*Bsz + b)*NCH + c]);
        float L = 0.f;
        for (int c = 0; c < NCH; ++c) {
            cf2[c] = expf(g_mP[(0*Bsz + b)*NCH + c] - M);
            L += g_lP[(0*Bsz + b)*NCH + c] * cf2[c];
        }
        for (int c = 0; c < NCH; ++c) cf2[c] /= L;
    }
    {
        float M = __int_as_float(0xff800000);
        for (int c = 0; c < NCH; ++c) M = fmaxf(M, g_mP[(1*Bsz + b)*NCH + c]);
        float L = 0.f;
        for (int c = 0; c < NCH; ++c) {
            cf1[c] = expf(g_mP[(1*Bsz + b)*NCH + c] - M);
            L += g_lP[(1*Bsz + b)*NCH + c] * cf1[c];
        }
        for (int c = 0; c < NCH; ++c) cf1[c] /= L;
    }

    #pragma unroll
    for (int j = 0; j < 3; ++j) {
        int d = t + j*512;
        float s2 = 0.f, s1 = 0.f;
        #pragma unroll
        for (int c = 0; c < NCH; ++c) {
            s2 += cf2[c] * g_accP[((size_t)(0*Bsz + b)*NCH + c)*Dsz + d];
            s1 += cf1[c] * g_accP[((size_t)(1*Bsz + b)*NCH + c)*Dsz + d];
        }
        float* fb = g_feat + (size_t)b * FEAT;
        fb[d]            = s2;                                   // sent_attn2
        fb[Dsz + d]      = s1;                                   // sent_attn1
        fb[2*Dsz + d]    = x[(size_t)b * Ssz * Dsz + d];         // out_per_seq[:,0]
        fb[3*Dsz + d]    = g_ent[(size_t)(0*Bsz + b)*Dsz + d];   // entity2
    }
}

// =====================================================================
// Kernel E: H = F @ W1^T  (M=64, N=1024, K=6144), split-K partials
// BM=64, BN=128, BK=16, 256 threads, 4x8 microtile
// =====================================================================
__global__ void __launch_bounds__(256) k_mlp(const float* __restrict__ W1)
{
    __shared__ float Fs[16][64];
    __shared__ float Ws[16][128];
    int n0 = blockIdx.x * 128;
    int k0 = blockIdx.y * (FEAT / MKSPLIT);   // 384
    int t = threadIdx.x;
    int tx = t & 15, ty = t >> 4;
    float acc[4][8];
    #pragma unroll
    for (int i = 0; i < 4; ++i)
        #pragma unroll
        for (int j = 0; j < 8; ++j) acc[i][j] = 0.f;

    int fr  = t >> 2;          // 0..63
    int fkp = (t & 3) * 4;     // 0,4,8,12
    int wr  = t >> 1;          // 0..127
    int wkp = (t & 1) * 8;     // 0,8

    for (int kt = 0; kt < (FEAT / MKSPLIT) / 16; ++kt) {   // 24 steps
        int kb = k0 + kt * 16;
        float4 f0 = *(const float4*)(g_feat + (size_t)fr*FEAT + kb + fkp);
        float4 w0 = *(const float4*)(W1 + (size_t)(n0 + wr)*FEAT + kb + wkp);
        float4 w1 = *(const float4*)(W1 + (size_t)(n0 + wr)*FEAT + kb + wkp + 4);
        __syncthreads();
        Fs[fkp+0][fr]=f0.x; Fs[fkp+1][fr]=f0.y; Fs[fkp+2][fr]=f0.z; Fs[fkp+3][fr]=f0.w;
        Ws[wkp+0][wr]=w0.x; Ws[wkp+1][wr]=w0.y; Ws[wkp+2][wr]=w0.z; Ws[wkp+3][wr]=w0.w;
        Ws[wkp+4][wr]=w1.x; Ws[wkp+5][wr]=w1.y; Ws[wkp+6][wr]=w1.z; Ws[wkp+7][wr]=w1.w;
        __syncthreads();
        #pragma unroll
        for (int kk = 0; kk < 16; ++kk) {
            float4 a0 = *(const float4*)&Fs[kk][ty*4];
            float4 b0 = *(const float4*)&Ws[kk][tx*8];
            float4 b1 = *(const float4*)&Ws[kk][tx*8+4];
            float av[4] = {a0.x,a0.y,a0.z,a0.w};
            float bv[8] = {b0.x,b0.y,b0.z,b0.w,b1.x,b1.y,b1.z,b1.w};
            #pragma unroll
            for (int i = 0; i < 4; ++i)
                #pragma unroll
                for (int j = 0; j < 8; ++j)
                    acc[i][j] += av[i]*bv[j];
        }
    }
    #pragma unroll
    for (int i = 0; i < 4; ++i) {
        int m = ty*4 + i;
        float* dst = g_hp + ((size_t)blockIdx.y * Bsz + m)*H1 + n0 + tx*8;
        *(float4*)dst       = make_float4(acc[i][0],acc[i][1],acc[i][2],acc[i][3]);
        *(float4*)(dst + 4) = make_float4(acc[i][4],acc[i][5],acc[i][6],acc[i][7]);
    }
}

// =====================================================================
// Kernel F: bias + leaky + W2 dot + b2
// =====================================================================
__global__ void k_final(const float* __restrict__ b1, const float* __restrict__ alpha,
                        const float* __restrict__ W2, const float* __restrict__ b2,
                        float* __restrict__ out)
{
    int b = blockIdx.x, t = threadIdx.x;   // 256 threads
    float a = alpha[0];
    float partial = 0.f;
    for (int j = t; j < H1; j += 256) {
        float h = b1[j];
        #pragma unroll
        for (int p = 0; p < MKSPLIT; ++p) h += g_hp[((size_t)p * Bsz + b)*H1 + j];
        h = (h >= 0.f) ? h : a*h;
        partial += W2[j]*h;
    }
    __shared__ float rs[8];
    int lane = t & 31, wid = t >> 5;
    #pragma unroll
    for (int o = 16; o > 0; o >>= 1) partial += __shfl_down_sync(0xffffffffu, partial, o);
    if (lane == 0) rs[wid] = partial;
    __syncthreads();
    if (t == 0) {
        float s = 0.f;
        #pragma unroll
        for (int w = 0; w < 8; ++w) s += rs[w];
        out[b] = s + b2[0];
    }
}

// =====================================================================
extern "C" void kernel_launch(void* const* d_in, const int* in_sizes, int n_in,
                              void* d_out, int out_size)
{
    const float* x     = (const float*)d_in[0];
    const float* Win   = (const float*)d_in[1];
    const float* W1    = (const float*)d_in[2];
    const float* b1    = (const float*)d_in[3];
    const float* alpha = (const float*)d_in[4];
    const float* W2    = (const float*)d_in[5];
    const float* b2    = (const float*)d_in[6];
    const int*   locs  = (const int*)d_in[7];
    const int*   seps  = (const int*)d_in[8];
    float* out = (float*)d_out;

    k_entities<<<Bsz, 512>>>(x, locs);
    k_qgemm<<<dim3(Dsz/128, QKSPLIT), 256>>>(Win);
    k_qreduce<<<(2*Bsz*Dsz)/512, 512>>>();
    k_attn<<<Bsz*NCH, 384>>>(x, locs, seps);
    k_merge<<<Bsz, 512>>>(x);
    k_mlp<<<dim3(H1/128, MKSPLIT), 256>>>(W1);
    k_final<<<Bsz, 256>>>(b1, alpha, W2, b2, out);
}

// round 10
// speedup vs baseline: 1.1592x; 1.1592x over previous
#include <cuda_runtime.h>
#include <math.h>

#define Bsz 64
#define Ssz 512
#define Dsz 1536
#define FEAT (4*Dsz)      // 6144
#define H1 1024
#define NCH 8             // s-chunks in attention kernel
#define CHS (Ssz/NCH)     // 64
#define QKSPLIT 24        // split-K for Q gemm (K=1536 -> 64 per split)
#define MKSPLIT 16        // split-K for MLP gemm (K=6144 -> 384 per split)

// ---------------- scratch (static device globals; no allocation) ----------------
__device__ float g_ent[2*Bsz*Dsz];                 // rows: [0..63]=entity2, [64..127]=entity1
__device__ float g_qp[QKSPLIT*2*Bsz*Dsz];          // Q gemm partials [ks][128][1536]
__device__ float g_q[2*Bsz*Dsz];                   // q rows: [b]=q2, [64+b]=q1
__device__ float g_accP[2*Bsz*NCH*Dsz];            // attention partial weighted sums
__device__ float g_mP[2*Bsz*NCH];
__device__ float g_lP[2*Bsz*NCH];
__device__ float g_feat[Bsz*FEAT];
__device__ float g_hp[MKSPLIT*Bsz*H1];             // MLP partials

// =====================================================================
// Kernel A: entity masked means (entity spans are tiny: <=7 rows each)
// =====================================================================
__global__ void k_entities(const float* __restrict__ x, const int* __restrict__ locs)
{
    int b = blockIdx.x;
    int l0 = locs[b*4+0], l1 = locs[b*4+1], l2 = locs[b*4+2], l3 = locs[b*4+3];
    float c1 = (float)((l1 - l0 - 1) > 0 ? (l1 - l0 - 1) : 1);
    float c2 = (float)((l3 - l2 - 1) > 0 ? (l3 - l2 - 1) : 1);
    const float* xb = x + (size_t)b * Ssz * Dsz;
    for (int d = threadIdx.x; d < Dsz; d += blockDim.x) {
        float s1 = 0.f, s2 = 0.f;
        for (int s = l0 + 1; s < l1; ++s) s1 += xb[(size_t)s*Dsz + d];
        for (int s = l2 + 1; s < l3; ++s) s2 += xb[(size_t)s*Dsz + d];
        g_ent[(size_t)(0*Bsz + b)*Dsz + d] = s2 / c2;   // entity2
        g_ent[(size_t)(1*Bsz + b)*Dsz + d] = s1 / c1;   // entity1
    }
}

// =====================================================================
// Kernel B: Q = E @ W_in^T   (M=128, N=1536, K=1536), split-K partials
// BM=128, BN=128, BK=16, 256 threads, 8x8 microtile; K=64 per split
// =====================================================================
__global__ void __launch_bounds__(256) k_qgemm(const float* __restrict__ Win)
{
    __shared__ float Es[16][128];
    __shared__ float Ws[16][128];
    int n0 = blockIdx.x * 128;
    int k0 = blockIdx.y * (Dsz / QKSPLIT);   // 64
    int t = threadIdx.x;
    int tx = t & 15, ty = t >> 4;
    float acc[8][8];
    #pragma unroll
    for (int i = 0; i < 8; ++i)
        #pragma unroll
        for (int j = 0; j < 8; ++j) acc[i][j] = 0.f;

    int r  = t >> 1;
    int kp = (t & 1) * 8;

    for (int kt = 0; kt < (Dsz / QKSPLIT) / 16; ++kt) {   // 4 steps
        int kb = k0 + kt * 16;
        float4 e0 = *(const float4*)(g_ent + (size_t)r*Dsz + kb + kp);
        float4 e1 = *(const float4*)(g_ent + (size_t)r*Dsz + kb + kp + 4);
        float4 w0 = *(const float4*)(Win + (size_t)(n0 + r)*Dsz + kb + kp);
        float4 w1 = *(const float4*)(Win + (size_t)(n0 + r)*Dsz + kb + kp + 4);
        __syncthreads();
        Es[kp+0][r]=e0.x; Es[kp+1][r]=e0.y; Es[kp+2][r]=e0.z; Es[kp+3][r]=e0.w;
        Es[kp+4][r]=e1.x; Es[kp+5][r]=e1.y; Es[kp+6][r]=e1.z; Es[kp+7][r]=e1.w;
        Ws[kp+0][r]=w0.x; Ws[kp+1][r]=w0.y; Ws[kp+2][r]=w0.z; Ws[kp+3][r]=w0.w;
        Ws[kp+4][r]=w1.x; Ws[kp+5][r]=w1.y; Ws[kp+6][r]=w1.z; Ws[kp+7][r]=w1.w;
        __syncthreads();
        #pragma unroll
        for (int kk = 0; kk < 16; ++kk) {
            float4 a0 = *(const float4*)&Es[kk][ty*8];
            float4 a1 = *(const float4*)&Es[kk][ty*8+4];
            float4 b0 = *(const float4*)&Ws[kk][tx*8];
            float4 b1 = *(const float4*)&Ws[kk][tx*8+4];
            float av[8] = {a0.x,a0.y,a0.z,a0.w,a1.x,a1.y,a1.z,a1.w};
            float bv[8] = {b0.x,b0.y,b0.z,b0.w,b1.x,b1.y,b1.z,b1.w};
            #pragma unroll
            for (int i = 0; i < 8; ++i)
                #pragma unroll
                for (int j = 0; j < 8; ++j)
                    acc[i][j] += av[i]*bv[j];
        }
    }
    #pragma unroll
    for (int i = 0; i < 8; ++i) {
        int m = ty*8 + i;
        float* dst = g_qp + ((size_t)blockIdx.y * 128 + m)*Dsz + n0 + tx*8;
        *(float4*)dst       = make_float4(acc[i][0],acc[i][1],acc[i][2],acc[i][3]);
        *(float4*)(dst + 4) = make_float4(acc[i][4],acc[i][5],acc[i][6],acc[i][7]);
    }
}

__global__ void k_qreduce()
{
    int i = blockIdx.x * 512 + threadIdx.x;   // 384*512 == 2*Bsz*Dsz
    float s = 0.f;
    #pragma unroll
    for (int p = 0; p < QKSPLIT; ++p) s += g_qp[(size_t)p * (2*Bsz*Dsz) + i];
    g_q[i] = s;
}

// =====================================================================
// Kernel C: fused scores + online softmax + weighted accumulation
// grid = 64 batches * 8 s-chunks, 384 threads, thread owns 4 contiguous chans.
// Group-max softmax update: one rescale per 8-row group, __expf throughout.
// =====================================================================
__global__ void __launch_bounds__(384) k_attn(const float* __restrict__ x,
                                              const int* __restrict__ locs,
                                              const int* __restrict__ seps)
{
    int blk = blockIdx.x;
    int b = blk >> 3, ch = blk & 7;
    int t = threadIdx.x;
    int L0 = locs[b*4+0], L1 = locs[b*4+1], L2 = locs[b*4+2], L3 = locs[b*4+3];
    int S0 = seps[b*2+0], S1 = seps[b*2+1];

    float4 q2v = *(const float4*)(g_q + (size_t)b*Dsz + 4*t);
    float4 q1v = *(const float4*)(g_q + (size_t)(Bsz + b)*Dsz + 4*t);

    float acc2[4] = {0.f,0.f,0.f,0.f}, acc1[4] = {0.f,0.f,0.f,0.f};
    const float NEGINF = __int_as_float(0xff800000);
    float m2v = NEGINF, l2v = 0.f, m1v = NEGINF, l1v = 0.f;

    __shared__ float red[16][13];   // padded: stride 13 kills bank conflicts
    __shared__ float fin[16];

    const float* xb = x + ((size_t)b * Ssz + (size_t)ch * CHS) * Dsz;
    int lane = t & 31, wid = t >> 5;   // 12 warps

    for (int g = 0; g < CHS/8; ++g) {
        int sbase = ch*CHS + g*8;
        float xr[8][4];
        float p[16];
        bool i1[8], i2[8];
        #pragma unroll
        for (int u = 0; u < 8; ++u) {
            int s = sbase + u;
            i1[u] = (s <= L0) || ((s >= L1) && (s < S0));
            i2[u] = ((s >= S1) && (s <= L2)) || (s >= L3);
            if (i1[u] || i2[u]) {
                float4 v = *(const float4*)(xb + (size_t)(g*8 + u) * Dsz + 4*t);
                xr[u][0]=v.x; xr[u][1]=v.y; xr[u][2]=v.z; xr[u][3]=v.w;
            } else {
                xr[u][0]=0.f; xr[u][1]=0.f; xr[u][2]=0.f; xr[u][3]=0.f;
            }
            float d2 = q2v.x*xr[u][0] + q2v.y*xr[u][1] + q2v.z*xr[u][2] + q2v.w*xr[u][3];
            float d1 = q1v.x*xr[u][0] + q1v.y*xr[u][1] + q1v.z*xr[u][2] + q1v.w*xr[u][3];
            p[2*u]   = i2[u] ? d2 : 0.f;
            p[2*u+1] = i1[u] ? d1 : 0.f;
        }
        // two-stage reduce of 16 values over 384 threads
        #pragma unroll
        for (int v = 0; v < 16; ++v) {
            float val = p[v];
            val += __shfl_down_sync(0xffffffffu, val, 16);
            val += __shfl_down_sync(0xffffffffu, val, 8);
            val += __shfl_down_sync(0xffffffffu, val, 4);
            val += __shfl_down_sync(0xffffffffu, val, 2);
            val += __shfl_down_sync(0xffffffffu, val, 1);
            if (lane == 0) red[v][wid] = val;
        }
        __syncthreads();
        if (wid == 0 && lane < 16) {
            float ssum = 0.f;
            #pragma unroll
            for (int w = 0; w < 12; ++w) ssum += red[lane][w];
            fin[lane] = ssum;
        }
        __syncthreads();

        // ---- group-max online softmax update (one rescale per group) ----
        {
            bool any2 = false;
            float gmax = NEGINF;
            #pragma unroll
            for (int u = 0; u < 8; ++u) if (i2[u]) { any2 = true; gmax = fmaxf(gmax, fin[2*u]); }
            if (any2) {
                float nm = fmaxf(m2v, gmax);
                float scale = __expf(m2v - nm);     // m2v=-inf -> 0
                l2v *= scale;
                #pragma unroll
                for (int j = 0; j < 4; ++j) acc2[j] *= scale;
                #pragma unroll
                for (int u = 0; u < 8; ++u) {
                    if (i2[u]) {
                        float w = __expf(fin[2*u] - nm);
                        l2v += w;
                        #pragma unroll
                        for (int j = 0; j < 4; ++j) acc2[j] += w*xr[u][j];
                    }
                }
                m2v = nm;
            }
        }
        {
            bool any1 = false;
            float gmax = NEGINF;
            #pragma unroll
            for (int u = 0; u < 8; ++u) if (i1[u]) { any1 = true; gmax = fmaxf(gmax, fin[2*u+1]); }
            if (any1) {
                float nm = fmaxf(m1v, gmax);
                float scale = __expf(m1v - nm);
                l1v *= scale;
                #pragma unroll
                for (int j = 0; j < 4; ++j) acc1[j] *= scale;
                #pragma unroll
                for (int u = 0; u < 8; ++u) {
                    if (i1[u]) {
                        float w = __expf(fin[2*u+1] - nm);
                        l1v += w;
                        #pragma unroll
                        for (int j = 0; j < 4; ++j) acc1[j] += w*xr[u][j];
                    }
                }
                m1v = nm;
            }
        }
        __syncthreads();   // protect fin before next group's overwrite
    }

    size_t base2 = ((size_t)(0*Bsz + b)*NCH + ch)*Dsz + 4*t;
    size_t base1 = ((size_t)(1*Bsz + b)*NCH + ch)*Dsz + 4*t;
    *(float4*)(g_accP + base2) = make_float4(acc2[0],acc2[1],acc2[2],acc2[3]);
    *(float4*)(g_accP + base1) = make_float4(acc1[0],acc1[1],acc1[2],acc1[3]);
    if (t == 0) {
        g_mP[(0*Bsz + b)*NCH + ch] = m2v;  g_lP[(0*Bsz + b)*NCH + ch] = l2v;
        g_mP[(1*Bsz + b)*NCH + ch] = m1v;  g_lP[(1*Bsz + b)*NCH + ch] = l1v;
    }
}

// =====================================================================
// Kernel D: merge chunk partials + assemble feat = [attn2, attn1, x[:,0], entity2]
// =====================================================================
__global__ void k_merge(const float* __restrict__ x)
{
    int b = blockIdx.x, t = threadIdx.x;   // 512 threads

    float cf2[NCH], cf1[NCH];
    {
        float M = __int_as_float(0xff800000);
        for (int c = 0; c < NCH; ++c) M = fmaxf(M, g_mP[(0*Bsz + b)*NCH + c]);
        float L = 0.f;
        for (int c = 0; c < NCH; ++c) {
            cf2[c] = __expf(g_mP[(0*Bsz + b)*NCH + c] - M);
            L += g_lP[(0*Bsz + b)*NCH + c] * cf2[c];
        }
        for (int c = 0; c < NCH; ++c) cf2[c] /= L;
    }
    {
        float M = __int_as_float(0xff800000);
        for (int c = 0; c < NCH; ++c) M = fmaxf(M, g_mP[(1*Bsz + b)*NCH + c]);
        float L = 0.f;
        for (int c = 0; c < NCH; ++c) {
            cf1[c] = __expf(g_mP[(1*Bsz + b)*NCH + c] - M);
            L += g_lP[(1*Bsz + b)*NCH + c] * cf1[c];
        }
        for (int c = 0; c < NCH; ++c) cf1[c] /= L;
    }

    #pragma unroll
    for (int j = 0; j < 3; ++j) {
        int d = t + j*512;
        float s2 = 0.f, s1 = 0.f;
        #pragma unroll
        for (int c = 0; c < NCH; ++c) {
            s2 += cf2[c] * g_accP[((size_t)(0*Bsz + b)*NCH + c)*Dsz + d];
            s1 += cf1[c] * g_accP[((size_t)(1*Bsz + b)*NCH + c)*Dsz + d];
        }
        float* fb = g_feat + (size_t)b * FEAT;
        fb[d]            = s2;                                   // sent_attn2
        fb[Dsz + d]      = s1;                                   // sent_attn1
        fb[2*Dsz + d]    = x[(size_t)b * Ssz * Dsz + d];         // out_per_seq[:,0]
        fb[3*Dsz + d]    = g_ent[(size_t)(0*Bsz + b)*Dsz + d];   // entity2
    }
}

// =====================================================================
// Kernel E: H = F @ W1^T  (M=64, N=1024, K=6144), split-K partials
// BM=64, BN=64, BK=16, 256 threads, 4x4 microtile; grid (16,16)=256 blocks
// =====================================================================
__global__ void __launch_bounds__(256) k_mlp(const float* __restrict__ W1)
{
    __shared__ float Fs[16][64];
    __shared__ float Ws[16][64];
    int n0 = blockIdx.x * 64;
    int k0 = blockIdx.y * (FEAT / MKSPLIT);   // 384
    int t = threadIdx.x;
    int tx = t & 15, ty = t >> 4;
    float acc[4][4];
    #pragma unroll
    for (int i = 0; i < 4; ++i)
        #pragma unroll
        for (int j = 0; j < 4; ++j) acc[i][j] = 0.f;

    int r  = t >> 2;          // 0..63
    int kp = (t & 3) * 4;     // 0,4,8,12

    for (int kt = 0; kt < (FEAT / MKSPLIT) / 16; ++kt) {   // 24 steps
        int kb = k0 + kt * 16;
        float4 f0 = *(const float4*)(g_feat + (size_t)r*FEAT + kb + kp);
        float4 w0 = *(const float4*)(W1 + (size_t)(n0 + r)*FEAT + kb + kp);
        __syncthreads();
        Fs[kp+0][r]=f0.x; Fs[kp+1][r]=f0.y; Fs[kp+2][r]=f0.z; Fs[kp+3][r]=f0.w;
        Ws[kp+0][r]=w0.x; Ws[kp+1][r]=w0.y; Ws[kp+2][r]=w0.z; Ws[kp+3][r]=w0.w;
        __syncthreads();
        #pragma unroll
        for (int kk = 0; kk < 16; ++kk) {
            float4 a0 = *(const float4*)&Fs[kk][ty*4];
            float4 b0 = *(const float4*)&Ws[kk][tx*4];
            float av[4] = {a0.x,a0.y,a0.z,a0.w};
            float bv[4] = {b0.x,b0.y,b0.z,b0.w};
            #pragma unroll
            for (int i = 0; i < 4; ++i)
                #pragma unroll
                for (int j = 0; j < 4; ++j)
                    acc[i][j] += av[i]*bv[j];
        }
    }
    #pragma unroll
    for (int i = 0; i < 4; ++i) {
        int m = ty*4 + i;
        float* dst = g_hp + ((size_t)blockIdx.y * Bsz + m)*H1 + n0 + tx*4;
        *(float4*)dst = make_float4(acc[i][0],acc[i][1],acc[i][2],acc[i][3]);
    }
}

// =====================================================================
// Kernel F: bias + leaky + W2 dot + b2
// =====================================================================
__global__ void k_final(const float* __restrict__ b1, const float* __restrict__ alpha,
                        const float* __restrict__ W2, const float* __restrict__ b2,
                        float* __restrict__ out)
{
    int b = blockIdx.x, t = threadIdx.x;   // 256 threads
    float a = alpha[0];
    float partial = 0.f;
    for (int j = t; j < H1; j += 256) {
        float h = b1[j];
        #pragma unroll
        for (int p = 0; p < MKSPLIT; ++p) h += g_hp[((size_t)p * Bsz + b)*H1 + j];
        h = (h >= 0.f) ? h : a*h;
        partial += W2[j]*h;
    }
    __shared__ float rs[8];
    int lane = t & 31, wid = t >> 5;
    #pragma unroll
    for (int o = 16; o > 0; o >>= 1) partial += __shfl_down_sync(0xffffffffu, partial, o);
    if (lane == 0) rs[wid] = partial;
    __syncthreads();
    if (t == 0) {
        float s = 0.f;
        #pragma unroll
        for (int w = 0; w < 8; ++w) s += rs[w];
        out[b] = s + b2[0];
    }
}

// =====================================================================
extern "C" void kernel_launch(void* const* d_in, const int* in_sizes, int n_in,
                              void* d_out, int out_size)
{
    const float* x     = (const float*)d_in[0];
    const float* Win   = (const float*)d_in[1];
    const float* W1    = (const float*)d_in[2];
    const float* b1    = (const float*)d_in[3];
    const float* alpha = (const float*)d_in[4];
    const float* W2    = (const float*)d_in[5];
    const float* b2    = (const float*)d_in[6];
    const int*   locs  = (const int*)d_in[7];
    const int*   seps  = (const int*)d_in[8];
    float* out = (float*)d_out;

    k_entities<<<Bsz, 512>>>(x, locs);
    k_qgemm<<<dim3(Dsz/128, QKSPLIT), 256>>>(Win);
    k_qreduce<<<(2*Bsz*Dsz)/512, 512>>>();
    k_attn<<<Bsz*NCH, 384>>>(x, locs, seps);
    k_merge<<<Bsz, 512>>>(x);
    k_mlp<<<dim3(H1/64, MKSPLIT), 256>>>(W1);
    k_final<<<Bsz, 256>>>(b1, alpha, W2, b2, out);
}

// round 12
// speedup vs baseline: 1.2492x; 1.0776x over previous
#include <cuda_runtime.h>
#include <math.h>

#define Bsz 64
#define Ssz 512
#define Dsz 1536
#define FEAT (4*Dsz)      // 6144
#define H1 1024
#define NCH 8             // s-chunks in attention kernel
#define CHS (Ssz/NCH)     // 64
#define QKSPLIT 24        // split-K for Q gemm (K=1536 -> 64 per split)
#define MKSPLIT 16        // split-K for MLP gemm (K=6144 -> 384 per split)

// ---------------- scratch (static device globals; no allocation) ----------------
__device__ float g_ent[2*Bsz*Dsz];                 // rows: [0..63]=entity2, [64..127]=entity1
__device__ float g_qp[QKSPLIT*2*Bsz*Dsz];          // Q gemm partials [ks][128][1536]
__device__ float g_q[2*Bsz*Dsz];                   // q rows: [b]=q2, [64+b]=q1
__device__ float g_accP[2*Bsz*NCH*Dsz];            // attention partial weighted sums
__device__ float g_mP[2*Bsz*NCH];
__device__ float g_lP[2*Bsz*NCH];
__device__ float g_feat[Bsz*FEAT];
__device__ float g_hp[MKSPLIT*Bsz*H1];             // MLP partials

// =====================================================================
// Kernel A: entity masked means (entity spans are tiny: <=7 rows each)
// =====================================================================
__global__ void k_entities(const float* __restrict__ x, const int* __restrict__ locs)
{
    int b = blockIdx.x;
    int l0 = locs[b*4+0], l1 = locs[b*4+1], l2 = locs[b*4+2], l3 = locs[b*4+3];
    float c1 = (float)((l1 - l0 - 1) > 0 ? (l1 - l0 - 1) : 1);
    float c2 = (float)((l3 - l2 - 1) > 0 ? (l3 - l2 - 1) : 1);
    const float* xb = x + (size_t)b * Ssz * Dsz;
    for (int d = threadIdx.x; d < Dsz; d += blockDim.x) {
        float s1 = 0.f, s2 = 0.f;
        for (int s = l0 + 1; s < l1; ++s) s1 += xb[(size_t)s*Dsz + d];
        for (int s = l2 + 1; s < l3; ++s) s2 += xb[(size_t)s*Dsz + d];
        g_ent[(size_t)(0*Bsz + b)*Dsz + d] = s2 / c2;   // entity2
        g_ent[(size_t)(1*Bsz + b)*Dsz + d] = s1 / c1;   // entity1
    }
}

// =====================================================================
// Kernel B: Q = E @ W_in^T   (M=128, N=1536, K=1536), split-K partials
// BM=128, BN=128, BK=16, 256 threads, 8x8 microtile; K=64 per split
// =====================================================================
__global__ void __launch_bounds__(256) k_qgemm(const float* __restrict__ Win)
{
    __shared__ float Es[16][128];
    __shared__ float Ws[16][128];
    int n0 = blockIdx.x * 128;
    int k0 = blockIdx.y * (Dsz / QKSPLIT);   // 64
    int t = threadIdx.x;
    int tx = t & 15, ty = t >> 4;
    float acc[8][8];
    #pragma unroll
    for (int i = 0; i < 8; ++i)
        #pragma unroll
        for (int j = 0; j < 8; ++j) acc[i][j] = 0.f;

    int r  = t >> 1;
    int kp = (t & 1) * 8;

    for (int kt = 0; kt < (Dsz / QKSPLIT) / 16; ++kt) {   // 4 steps
        int kb = k0 + kt * 16;
        float4 e0 = *(const float4*)(g_ent + (size_t)r*Dsz + kb + kp);
        float4 e1 = *(const float4*)(g_ent + (size_t)r*Dsz + kb + kp + 4);
        float4 w0 = *(const float4*)(Win + (size_t)(n0 + r)*Dsz + kb + kp);
        float4 w1 = *(const float4*)(Win + (size_t)(n0 + r)*Dsz + kb + kp + 4);
        __syncthreads();
        Es[kp+0][r]=e0.x; Es[kp+1][r]=e0.y; Es[kp+2][r]=e0.z; Es[kp+3][r]=e0.w;
        Es[kp+4][r]=e1.x; Es[kp+5][r]=e1.y; Es[kp+6][r]=e1.z; Es[kp+7][r]=e1.w;
        Ws[kp+0][r]=w0.x; Ws[kp+1][r]=w0.y; Ws[kp+2][r]=w0.z; Ws[kp+3][r]=w0.w;
        Ws[kp+4][r]=w1.x; Ws[kp+5][r]=w1.y; Ws[kp+6][r]=w1.z; Ws[kp+7][r]=w1.w;
        __syncthreads();
        #pragma unroll
        for (int kk = 0; kk < 16; ++kk) {
            float4 a0 = *(const float4*)&Es[kk][ty*8];
            float4 a1 = *(const float4*)&Es[kk][ty*8+4];
            float4 b0 = *(const float4*)&Ws[kk][tx*8];
            float4 b1 = *(const float4*)&Ws[kk][tx*8+4];
            float av[8] = {a0.x,a0.y,a0.z,a0.w,a1.x,a1.y,a1.z,a1.w};
            float bv[8] = {b0.x,b0.y,b0.z,b0.w,b1.x,b1.y,b1.z,b1.w};
            #pragma unroll
            for (int i = 0; i < 8; ++i)
                #pragma unroll
                for (int j = 0; j < 8; ++j)
                    acc[i][j] += av[i]*bv[j];
        }
    }
    #pragma unroll
    for (int i = 0; i < 8; ++i) {
        int m = ty*8 + i;
        float* dst = g_qp + ((size_t)blockIdx.y * 128 + m)*Dsz + n0 + tx*8;
        *(float4*)dst       = make_float4(acc[i][0],acc[i][1],acc[i][2],acc[i][3]);
        *(float4*)(dst + 4) = make_float4(acc[i][4],acc[i][5],acc[i][6],acc[i][7]);
    }
}

__global__ void k_qreduce()
{
    int i = blockIdx.x * 512 + threadIdx.x;   // 384*512 == 2*Bsz*Dsz
    float s = 0.f;
    #pragma unroll
    for (int p = 0; p < QKSPLIT; ++p) s += g_qp[(size_t)p * (2*Bsz*Dsz) + i];
    g_q[i] = s;
}

// =====================================================================
// Kernel C: fused scores + online softmax + weighted accumulation.
// KEY: seps are fixed at (S/2-1, S/2) => imp1 mask lives entirely in rows
// [0, S/2), imp2 entirely in [S/2, S). Chunks 0..3 process ONLY pool1,
// chunks 4..7 ONLY pool2: one query, one mask, one accumulator per block.
// Halves dot FMAs, halves SHFL reduce (8 values not 16), halves epilogue.
// =====================================================================
__global__ void __launch_bounds__(384) k_attn(const float* __restrict__ x,
                                              const int* __restrict__ locs,
                                              const int* __restrict__ seps)
{
    int blk = blockIdx.x;
    int b = blk >> 3, ch = blk & 7;
    int t = threadIdx.x;
    bool pool1 = (ch < NCH/2);    // rows < S/2 -> imp1; else imp2
    int L0 = locs[b*4+0], L1 = locs[b*4+1], L2 = locs[b*4+2], L3 = locs[b*4+3];
    int S0 = seps[b*2+0], S1 = seps[b*2+1];

    // pool1 uses q1 (row Bsz+b), pool2 uses q2 (row b)
    const float* qrow = g_q + (size_t)(pool1 ? (Bsz + b) : b) * Dsz;
    float4 qv = *(const float4*)(qrow + 4*t);

    float acc[4] = {0.f,0.f,0.f,0.f};
    const float NEGINF = __int_as_float(0xff800000);
    float mv = NEGINF, lv = 0.f;

    __shared__ float red[8][13];   // padded stride
    __shared__ float fin[8];

    const float* xb = x + ((size_t)b * Ssz + (size_t)ch * CHS) * Dsz;
    int lane = t & 31, wid = t >> 5;   // 12 warps

    for (int g = 0; g < CHS/8; ++g) {
        int sbase = ch*CHS + g*8;
        float xr[8][4];
        float p[8];
        bool in[8];
        #pragma unroll
        for (int u = 0; u < 8; ++u) {
            int s = sbase + u;
            in[u] = pool1 ? ((s <= L0) || ((s >= L1) && (s < S0)))
                          : (((s >= S1) && (s <= L2)) || (s >= L3));
            if (in[u]) {
                float4 v = *(const float4*)(xb + (size_t)(g*8 + u) * Dsz + 4*t);
                xr[u][0]=v.x; xr[u][1]=v.y; xr[u][2]=v.z; xr[u][3]=v.w;
            } else {
                xr[u][0]=0.f; xr[u][1]=0.f; xr[u][2]=0.f; xr[u][3]=0.f;
            }
            float d = qv.x*xr[u][0] + qv.y*xr[u][1] + qv.z*xr[u][2] + qv.w*xr[u][3];
            p[u] = in[u] ? d : 0.f;
        }
        // two-stage reduce of 8 values over 384 threads
        #pragma unroll
        for (int v = 0; v < 8; ++v) {
            float val = p[v];
            val += __shfl_down_sync(0xffffffffu, val, 16);
            val += __shfl_down_sync(0xffffffffu, val, 8);
            val += __shfl_down_sync(0xffffffffu, val, 4);
            val += __shfl_down_sync(0xffffffffu, val, 2);
            val += __shfl_down_sync(0xffffffffu, val, 1);
            if (lane == 0) red[v][wid] = val;
        }
        __syncthreads();
        if (wid == 0 && lane < 8) {
            float ssum = 0.f;
            #pragma unroll
            for (int w = 0; w < 12; ++w) ssum += red[lane][w];
            fin[lane] = ssum;
        }
        __syncthreads();

        // ---- group-max online softmax update (one rescale per group) ----
        {
            bool any = false;
            float gmax = NEGINF;
            #pragma unroll
            for (int u = 0; u < 8; ++u) if (in[u]) { any = true; gmax = fmaxf(gmax, fin[u]); }
            if (any) {
                float nm = fmaxf(mv, gmax);
                float scale = __expf(mv - nm);     // mv=-inf -> 0
                lv *= scale;
                #pragma unroll
                for (int j = 0; j < 4; ++j) acc[j] *= scale;
                #pragma unroll
                for (int u = 0; u < 8; ++u) {
                    if (in[u]) {
                        float w = __expf(fin[u] - nm);
                        lv += w;
                        #pragma unroll
                        for (int j = 0; j < 4; ++j) acc[j] += w*xr[u][j];
                    }
                }
                mv = nm;
            }
        }
        __syncthreads();   // protect fin before next group's overwrite
    }

    // write ONLY the active pool's slot (merge reads matching chunks only)
    int pi = pool1 ? 1 : 0;     // layout: [0]=pool2, [1]=pool1
    size_t base = ((size_t)(pi*Bsz + b)*NCH + ch)*Dsz + 4*t;
    *(float4*)(g_accP + base) = make_float4(acc[0],acc[1],acc[2],acc[3]);
    if (t == 0) {
        g_mP[(pi*Bsz + b)*NCH + ch] = mv;
        g_lP[(pi*Bsz + b)*NCH + ch] = lv;
    }
}

// =====================================================================
// Kernel D: merge chunk partials + assemble feat = [attn2, attn1, x[:,0], entity2]
// pool2 lives in chunks 4..7, pool1 in chunks 0..3 (see k_attn).
// =====================================================================
__global__ void k_merge(const float* __restrict__ x)
{
    int b = blockIdx.x, t = threadIdx.x;   // 512 threads

    float cf2[NCH/2], cf1[NCH/2];
    {
        float M = __int_as_float(0xff800000);
        for (int i = 0; i < NCH/2; ++i) M = fmaxf(M, g_mP[(0*Bsz + b)*NCH + (NCH/2 + i)]);
        float L = 0.f;
        for (int i = 0; i < NCH/2; ++i) {
            int c = NCH/2 + i;
            cf2[i] = __expf(g_mP[(0*Bsz + b)*NCH + c] - M);
            L += g_lP[(0*Bsz + b)*NCH + c] * cf2[i];
        }
        for (int i = 0; i < NCH/2; ++i) cf2[i] /= L;
    }
    {
        float M = __int_as_float(0xff800000);
        for (int i = 0; i < NCH/2; ++i) M = fmaxf(M, g_mP[(1*Bsz + b)*NCH + i]);
        float L = 0.f;
        for (int i = 0; i < NCH/2; ++i) {
            cf1[i] = __expf(g_mP[(1*Bsz + b)*NCH + i] - M);
            L += g_lP[(1*Bsz + b)*NCH + i] * cf1[i];
        }
        for (int i = 0; i < NCH/2; ++i) cf1[i] /= L;
    }

    #pragma unroll
    for (int j = 0; j < 3; ++j) {
        int d = t + j*512;
        float s2 = 0.f, s1 = 0.f;
        #pragma unroll
        for (int i = 0; i < NCH/2; ++i) {
            s2 += cf2[i] * g_accP[((size_t)(0*Bsz + b)*NCH + (NCH/2 + i))*Dsz + d];
            s1 += cf1[i] * g_accP[((size_t)(1*Bsz + b)*NCH + i)*Dsz + d];
        }
        float* fb = g_feat + (size_t)b * FEAT;
        fb[d]            = s2;                                   // sent_attn2
        fb[Dsz + d]      = s1;                                   // sent_attn1
        fb[2*Dsz + d]    = x[(size_t)b * Ssz * Dsz + d];         // out_per_seq[:,0]
        fb[3*Dsz + d]    = g_ent[(size_t)(0*Bsz + b)*Dsz + d];   // entity2
    }
}

// =====================================================================
// Kernel E: H = F @ W1^T  (M=64, N=1024, K=6144), split-K partials
// BM=64, BN=64, BK=16, 256 threads, 4x4 microtile; grid (16,16)=256 blocks
// =====================================================================
__global__ void __launch_bounds__(256) k_mlp(const float* __restrict__ W1)
{
    __shared__ float Fs[16][64];
    __shared__ float Ws[16][64];
    int n0 = blockIdx.x * 64;
    int k0 = blockIdx.y * (FEAT / MKSPLIT);   // 384
    int t = threadIdx.x;
    int tx = t & 15, ty = t >> 4;
    float acc[4][4];
    #pragma unroll
    for (int i = 0; i < 4; ++i)
        #pragma unroll
        for (int j = 0; j < 4; ++j) acc[i][j] = 0.f;

    int r  = t >> 2;          // 0..63
    int kp = (t & 3) * 4;     // 0,4,8,12

    for (int kt = 0; kt < (FEAT / MKSPLIT) / 16; ++kt) {   // 24 steps
        int kb = k0 + kt * 16;
        float4 f0 = *(const float4*)(g_feat + (size_t)r*FEAT + kb + kp);
        float4 w0 = *(const float4*)(W1 + (size_t)(n0 + r)*FEAT + kb + kp);
        __syncthreads();
        Fs[kp+0][r]=f0.x; Fs[kp+1][r]=f0.y; Fs[kp+2][r]=f0.z; Fs[kp+3][r]=f0.w;
        Ws[kp+0][r]=w0.x; Ws[kp+1][r]=w0.y; Ws[kp+2][r]=w0.z; Ws[kp+3][r]=w0.w;
        __syncthreads();
        #pragma unroll
        for (int kk = 0; kk < 16; ++kk) {
            float4 a0 = *(const float4*)&Fs[kk][ty*4];
            float4 b0 = *(const float4*)&Ws[kk][tx*4];
            float av[4] = {a0.x,a0.y,a0.z,a0.w};
            float bv[4] = {b0.x,b0.y,b0.z,b0.w};
            #pragma unroll
            for (int i = 0; i < 4; ++i)
                #pragma unroll
                for (int j = 0; j < 4; ++j)
                    acc[i][j] += av[i]*bv[j];
        }
    }
    #pragma unroll
    for (int i = 0; i < 4; ++i) {
        int m = ty*4 + i;
        float* dst = g_hp + ((size_t)blockIdx.y * Bsz + m)*H1 + n0 + tx*4;
        *(float4*)dst = make_float4(acc[i][0],acc[i][1],acc[i][2],acc[i][3]);
    }
}

// =====================================================================
// Kernel F: bias + leaky + W2 dot + b2
// =====================================================================
__global__ void k_final(const float* __restrict__ b1, const float* __restrict__ alpha,
                        const float* __restrict__ W2, const float* __restrict__ b2,
                        float* __restrict__ out)
{
    int b = blockIdx.x, t = threadIdx.x;   // 256 threads
    float a = alpha[0];
    float partial = 0.f;
    for (int j = t; j < H1; j += 256) {
        float h = b1[j];
        #pragma unroll
        for (int p = 0; p < MKSPLIT; ++p) h += g_hp[((size_t)p * Bsz + b)*H1 + j];
        h = (h >= 0.f) ? h : a*h;
        partial += W2[j]*h;
    }
    __shared__ float rs[8];
    int lane = t & 31, wid = t >> 5;
    #pragma unroll
    for (int o = 16; o > 0; o >>= 1) partial += __shfl_down_sync(0xffffffffu, partial, o);
    if (lane == 0) rs[wid] = partial;
    __syncthreads();
    if (t == 0) {
        float s = 0.f;
        #pragma unroll
        for (int w = 0; w < 8; ++w) s += rs[w];
        out[b] = s + b2[0];
    }
}

// =====================================================================
extern "C" void kernel_launch(void* const* d_in, const int* in_sizes, int n_in,
                              void* d_out, int out_size)
{
    const float* x     = (const float*)d_in[0];
    const float* Win   = (const float*)d_in[1];
    const float* W1    = (const float*)d_in[2];
    const float* b1    = (const float*)d_in[3];
    const float* alpha = (const float*)d_in[4];
    const float* W2    = (const float*)d_in[5];
    const float* b2    = (const float*)d_in[6];
    const int*   locs  = (const int*)d_in[7];
    const int*   seps  = (const int*)d_in[8];
    float* out = (float*)d_out;

    k_entities<<<Bsz, 512>>>(x, locs);
    k_qgemm<<<dim3(Dsz/128, QKSPLIT), 256>>>(Win);
    k_qreduce<<<(2*Bsz*Dsz)/512, 512>>>();
    k_attn<<<Bsz*NCH, 384>>>(x, locs, seps);
    k_merge<<<Bsz, 512>>>(x);
    k_mlp<<<dim3(H1/64, MKSPLIT), 256>>>(W1);
    k_final<<<Bsz, 256>>>(b1, alpha, W2, b2, out);
}